// round 6
// baseline (speedup 1.0000x reference)
#include <cuda_runtime.h>
#include <math.h>

#define T_STEPS 4096
#define IN_SZ   512
#define H1      1024
#define H2      2048
#define OUT_SZ  512
#define NCTA    128

// ---------------- device scratch (static, no allocation) ----------------
__device__ float g_pre1[T_STEPS * 4 * H1];        //  64 MB
__device__ float g_pre2[T_STEPS * 4 * H2];        // 128 MB
__device__ float g_hist1[(T_STEPS + 1) * H1];     //  ~17 MB  slot t = h1[t-1], slot 0 = zeros
__device__ float g_hist2[(T_STEPS + 1) * H2];     //  ~34 MB
__device__ float g_mid[2 * OUT_SZ];               // head intermediate
__device__ unsigned g_arr1[T_STEPS];
__device__ unsigned g_arr2[T_STEPS];

// ---------------- helpers ----------------
__device__ __forceinline__ unsigned ld_acq_u32(const unsigned* p) {
    unsigned v;
    asm volatile("ld.acquire.gpu.global.u32 %0, [%1];" : "=r"(v) : "l"(p));
    return v;
}

__device__ __forceinline__ float4 ld_cg_f4(const float4* p) {
    float4 v;
    asm volatile("ld.global.cg.v4.f32 {%0,%1,%2,%3}, [%4];"
                 : "=f"(v.x), "=f"(v.y), "=f"(v.z), "=f"(v.w) : "l"(p));
    return v;
}

__device__ __forceinline__ void st_cg_f32(float* p, float v) {
    asm volatile("st.global.cg.f32 [%0], %1;" :: "l"(p), "f"(v));
}

__device__ __forceinline__ float sigmoidf_(float x) {
    return 1.0f / (1.0f + expf(-x));
}

// ---------------- init: zero barriers + h0 slots (runs every replay) ----------------
__global__ void init_kernel() {
    int i = blockIdx.x * blockDim.x + threadIdx.x;
    if (i < T_STEPS) { g_arr1[i] = 0u; g_arr2[i] = 0u; }
    if (i < H1) g_hist1[i] = 0.0f;
    if (i < H2) g_hist2[i] = 0.0f;
}

// ---------------- input-projection GEMM: C[M,N] = X[M,K] * W[N,K]^T + ba + bb ----------------
// MODE 0: X = input_seq -> g_pre1 ; MODE 1: X = g_hist1 + H1 (h1 history) -> g_pre2
template <int MODE>
__global__ void __launch_bounds__(256, 2)
gemm_bias_kernel(const float* __restrict__ Xin, const float* __restrict__ W,
                 const float* __restrict__ ba, const float* __restrict__ bb,
                 int N, int K) {
    float* C = (MODE == 0) ? g_pre1 : g_pre2;
    const float* X = (MODE == 0) ? Xin : (g_hist1 + H1);

    __shared__ float Xs[16][64];
    __shared__ float Ws[16][64];

    int tid = threadIdx.x;
    int tx = tid & 15;
    int ty = tid >> 4;
    int n0 = blockIdx.x * 64;
    int m0 = blockIdx.y * 64;

    float acc[4][4];
#pragma unroll
    for (int i = 0; i < 4; i++)
#pragma unroll
        for (int j = 0; j < 4; j++) acc[i][j] = 0.0f;

    for (int kk = 0; kk < K; kk += 16) {
#pragma unroll
        for (int i = tid; i < 1024; i += 256) {
            int r = i >> 4;
            int k = i & 15;
            Xs[k][r] = X[(size_t)(m0 + r) * K + kk + k];
            Ws[k][r] = W[(size_t)(n0 + r) * K + kk + k];
        }
        __syncthreads();
#pragma unroll
        for (int k = 0; k < 16; k++) {
            float4 a = *(const float4*)&Xs[k][ty * 4];
            float4 b = *(const float4*)&Ws[k][tx * 4];
            float av[4] = {a.x, a.y, a.z, a.w};
            float bv[4] = {b.x, b.y, b.z, b.w};
#pragma unroll
            for (int i = 0; i < 4; i++)
#pragma unroll
                for (int j = 0; j < 4; j++) acc[i][j] = fmaf(av[i], bv[j], acc[i][j]);
        }
        __syncthreads();
    }

#pragma unroll
    for (int i = 0; i < 4; i++) {
        int m = m0 + ty * 4 + i;
#pragma unroll
        for (int j = 0; j < 4; j++) {
            int n = n0 + tx * 4 + j;
            C[(size_t)m * N + n] = acc[i][j] + ba[n] + bb[n];
        }
    }
}

// ---------------- persistent LSTM recurrence ----------------
// 128 CTAs (single wave, co-resident). One warp owns one hidden unit; the
// cell state c lives in a lane-0 register for all 4096 steps.
// h history is write-once: step t reads slot t, writes slot t+1, arrives arr[t].
// Release: EVERY thread fences its own stores before the barrier, then tid 0
// publishes via atomicAdd; acquire: tid 0 ld.acquire spin, then __syncthreads.
template <int HD, int PHASE>
__global__ void __launch_bounds__(HD / 4, 1)
lstm_kernel(const float* __restrict__ whh) {
    constexpr int WARPS = HD / 128;
    const float* pre  = (PHASE == 0) ? g_pre1  : g_pre2;
    float*       hist = (PHASE == 0) ? g_hist1 : g_hist2;
    unsigned*    arr  = (PHASE == 0) ? g_arr1  : g_arr2;

    __shared__ float4 hs[HD / 4];

    int tid  = threadIdx.x;
    int wid  = tid >> 5;
    int lane = tid & 31;
    int u = blockIdx.x * WARPS + wid;

    const float4* wi = (const float4*)(whh + (size_t)(0 * HD + u) * HD);
    const float4* wf = (const float4*)(whh + (size_t)(1 * HD + u) * HD);
    const float4* wg = (const float4*)(whh + (size_t)(2 * HD + u) * HD);
    const float4* wo = (const float4*)(whh + (size_t)(3 * HD + u) * HD);

    float c = 0.0f;

    for (int t = 0; t < T_STEPS; t++) {
        // ---- acquire: wait for step t-1 completion across all CTAs ----
        if (t > 0 && tid == 0) {
            while (ld_acq_u32(&arr[t - 1]) < (unsigned)NCTA) { }
        }
        __syncthreads();

        // ---- stage h_prev (slot t) into SMEM, L1-bypassed ----
        const float4* hread = (const float4*)(hist + (size_t)t * HD);
        hs[tid] = ld_cg_f4(&hread[tid]);
        __syncthreads();

        // ---- 4 gate-row dot products ----
        float a0 = 0.f, a1 = 0.f, a2 = 0.f, a3 = 0.f;
#pragma unroll 4
        for (int i = 0; i < HD / 128; i++) {
            int c4 = (i << 5) + lane;
            float4 h4 = hs[c4];
            float4 w0 = wi[c4];
            a0 = fmaf(w0.x, h4.x, a0); a0 = fmaf(w0.y, h4.y, a0);
            a0 = fmaf(w0.z, h4.z, a0); a0 = fmaf(w0.w, h4.w, a0);
            float4 w1 = wf[c4];
            a1 = fmaf(w1.x, h4.x, a1); a1 = fmaf(w1.y, h4.y, a1);
            a1 = fmaf(w1.z, h4.z, a1); a1 = fmaf(w1.w, h4.w, a1);
            float4 w2 = wg[c4];
            a2 = fmaf(w2.x, h4.x, a2); a2 = fmaf(w2.y, h4.y, a2);
            a2 = fmaf(w2.z, h4.z, a2); a2 = fmaf(w2.w, h4.w, a2);
            float4 w3 = wo[c4];
            a3 = fmaf(w3.x, h4.x, a3); a3 = fmaf(w3.y, h4.y, a3);
            a3 = fmaf(w3.z, h4.z, a3); a3 = fmaf(w3.w, h4.w, a3);
        }
#pragma unroll
        for (int off = 16; off > 0; off >>= 1) {
            a0 += __shfl_xor_sync(0xFFFFFFFFu, a0, off);
            a1 += __shfl_xor_sync(0xFFFFFFFFu, a1, off);
            a2 += __shfl_xor_sync(0xFFFFFFFFu, a2, off);
            a3 += __shfl_xor_sync(0xFFFFFFFFu, a3, off);
        }

        // ---- state update + publish h into write-once slot t+1 ----
        if (lane == 0) {
            const float* prow = pre + (size_t)t * (4 * HD);
            float pi = prow[0 * HD + u] + a0;
            float pf = prow[1 * HD + u] + a1;
            float pg = prow[2 * HD + u] + a2;
            float po = prow[3 * HD + u] + a3;
            float iv = sigmoidf_(pi);
            float fv = sigmoidf_(pf);
            float gv = tanhf(pg);
            float ov = sigmoidf_(po);
            c = fv * c + iv * gv;
            float h = ov * tanhf(c);
            st_cg_f32(hist + (size_t)(t + 1) * HD + u, h);
        }

        // ---- release: each storer drains its OWN store, then tid0 signals ----
        __threadfence();
        __syncthreads();
        if (tid == 0) {
            atomicAdd(&arr[t], 1u);
        }
    }
}

// ---------------- head: two matvecs on final h2 (slot T of g_hist2) ----------------
__global__ void __launch_bounds__(256) head1_kernel(const float* __restrict__ w,
                                                    const float* __restrict__ b) {
    int wid = threadIdx.x >> 5, lane = threadIdx.x & 31;
    int o = blockIdx.x * 8 + wid;                       // 128 blocks -> 1024 outputs
    const float4* wr = (const float4*)(w + (size_t)o * H2);
    const float4* hv = (const float4*)(g_hist2 + (size_t)T_STEPS * H2);
    float a = 0.f;
#pragma unroll
    for (int i = 0; i < 16; i++) {
        float4 W4 = wr[(i << 5) + lane];
        float4 Hh = hv[(i << 5) + lane];
        a = fmaf(W4.x, Hh.x, a); a = fmaf(W4.y, Hh.y, a);
        a = fmaf(W4.z, Hh.z, a); a = fmaf(W4.w, Hh.w, a);
    }
#pragma unroll
    for (int off = 16; off > 0; off >>= 1) a += __shfl_xor_sync(0xFFFFFFFFu, a, off);
    if (lane == 0) g_mid[o] = a + b[o];
}

__global__ void __launch_bounds__(256) head2_kernel(const float* __restrict__ w,
                                                    const float* __restrict__ b,
                                                    float* __restrict__ out) {
    int wid = threadIdx.x >> 5, lane = threadIdx.x & 31;
    int o = blockIdx.x * 8 + wid;                       // 64 blocks -> 512 outputs
    const float4* wr = (const float4*)(w + (size_t)o * (2 * OUT_SZ));
    const float4* mv = (const float4*)(g_mid);
    float a = 0.f;
#pragma unroll
    for (int i = 0; i < 8; i++) {
        float4 W4 = wr[(i << 5) + lane];
        float4 Mm = mv[(i << 5) + lane];
        a = fmaf(W4.x, Mm.x, a); a = fmaf(W4.y, Mm.y, a);
        a = fmaf(W4.z, Mm.z, a); a = fmaf(W4.w, Mm.w, a);
    }
#pragma unroll
    for (int off = 16; off > 0; off >>= 1) a += __shfl_xor_sync(0xFFFFFFFFu, a, off);
    if (lane == 0) out[o] = a + b[o];
}

// ---------------- launch ----------------
extern "C" void kernel_launch(void* const* d_in, const int* in_sizes, int n_in,
                              void* d_out, int out_size) {
    const float* input_seq = (const float*)d_in[0];
    const float* w_ih1     = (const float*)d_in[1];
    const float* w_hh1     = (const float*)d_in[2];
    const float* b_ih1     = (const float*)d_in[3];
    const float* b_hh1     = (const float*)d_in[4];
    const float* w_ih2     = (const float*)d_in[5];
    const float* w_hh2     = (const float*)d_in[6];
    const float* b_ih2     = (const float*)d_in[7];
    const float* b_hh2     = (const float*)d_in[8];
    const float* w_l1      = (const float*)d_in[9];
    const float* b_l1      = (const float*)d_in[10];
    const float* w_l2      = (const float*)d_in[11];
    const float* b_l2      = (const float*)d_in[12];
    float* out = (float*)d_out;

    // 1) reset barriers + zero h0 slots (every replay)
    init_kernel<<<16, 256>>>();

    // 2) lstm1 input projection: g_pre1[T, 4*H1]
    {
        dim3 grid(4 * H1 / 64, T_STEPS / 64);
        gemm_bias_kernel<0><<<grid, 256>>>(input_seq, w_ih1, b_ih1, b_hh1,
                                           4 * H1, IN_SZ);
    }

    // 3) lstm1 recurrence (persistent, 128 CTAs x 256 threads)
    lstm_kernel<H1, 0><<<NCTA, H1 / 4>>>(w_hh1);

    // 4) lstm2 input projection: g_pre2[T, 4*H2] from h1 history
    {
        dim3 grid(4 * H2 / 64, T_STEPS / 64);
        gemm_bias_kernel<1><<<grid, 256>>>(nullptr, w_ih2, b_ih2, b_hh2,
                                           4 * H2, H1);
    }

    // 5) lstm2 recurrence (persistent, 128 CTAs x 512 threads)
    lstm_kernel<H2, 1><<<NCTA, H2 / 4>>>(w_hh2);

    // 6) head on final h2
    head1_kernel<<<128, 256>>>(w_l1, b_l1);
    head2_kernel<<<64, 256>>>(w_l2, b_l2, out);
}

// round 10
// speedup vs baseline: 1.1181x; 1.1181x over previous
#include <cuda_runtime.h>
#include <cuda_fp16.h>
#include <math.h>

#define T_STEPS 4096
#define IN_SZ   512
#define H1      1024
#define H2      2048
#define OUT_SZ  512
#define NCTA    128

// ---------------- device scratch (static, no allocation) ----------------
__device__ float g_pre1[T_STEPS * 4 * H1];        //  64 MB
__device__ float g_pre2[T_STEPS * 4 * H2];        // 128 MB
__device__ float g_hist1[(T_STEPS + 1) * H1];     //  ~17 MB  slot t = h[t-1], slot 0 = zeros
__device__ float g_hist2[(T_STEPS + 1) * H2];     //  ~34 MB
__device__ float g_mid[2 * OUT_SZ];
__device__ unsigned g_arr1[T_STEPS];
__device__ unsigned g_arr2[T_STEPS];

// fp16 copies of recurrent weights, packed 4 halfs per uint2
__device__ uint2 g_whh1h[(size_t)4 * H1 * H1 / 4];   //  8 MB
__device__ uint2 g_whh2h[(size_t)4 * H2 * H2 / 4];   // 32 MB

// ---------------- helpers ----------------
__device__ __forceinline__ unsigned ld_acq_u32(const unsigned* p) {
    unsigned v;
    asm volatile("ld.acquire.gpu.global.u32 %0, [%1];" : "=r"(v) : "l"(p));
    return v;
}

__device__ __forceinline__ float4 ld_cg_f4(const float4* p) {
    float4 v;
    asm volatile("ld.global.cg.v4.f32 {%0,%1,%2,%3}, [%4];"
                 : "=f"(v.x), "=f"(v.y), "=f"(v.z), "=f"(v.w) : "l"(p));
    return v;
}

__device__ __forceinline__ void st_cg_f32(float* p, float v) {
    asm volatile("st.global.cg.f32 [%0], %1;" :: "l"(p), "f"(v));
}

__device__ __forceinline__ float sigmoidf_(float x) {
    return 1.0f / (1.0f + expf(-x));
}

// ---------------- init: zero barriers + h0 slots (runs every replay) ----------------
__global__ void init_kernel() {
    int i = blockIdx.x * blockDim.x + threadIdx.x;
    if (i < T_STEPS) { g_arr1[i] = 0u; g_arr2[i] = 0u; }
    if (i < H1) g_hist1[i] = 0.0f;
    if (i < H2) g_hist2[i] = 0.0f;
}

// ---------------- convert recurrent weights fp32 -> fp16 (once per replay) ----------------
__global__ void convert_w_kernel(const float* __restrict__ w1,
                                 const float* __restrict__ w2) {
    const size_t n1 = (size_t)4 * H1 * H1 / 4;
    const size_t n2 = (size_t)4 * H2 * H2 / 4;
    for (size_t i = (size_t)blockIdx.x * blockDim.x + threadIdx.x;
         i < n1 + n2; i += (size_t)gridDim.x * blockDim.x) {
        float4 v = (i < n1) ? ((const float4*)w1)[i] : ((const float4*)w2)[i - n1];
        __half2 lo = __floats2half2_rn(v.x, v.y);
        __half2 hi = __floats2half2_rn(v.z, v.w);
        uint2 o;
        o.x = *reinterpret_cast<unsigned*>(&lo);
        o.y = *reinterpret_cast<unsigned*>(&hi);
        if (i < n1) g_whh1h[i] = o;
        else        g_whh2h[i - n1] = o;
    }
}

// ---------------- input-projection GEMM: C[M,N] = X[M,K] * W[N,K]^T + ba + bb ----------------
template <int MODE>
__global__ void __launch_bounds__(256, 2)
gemm_bias_kernel(const float* __restrict__ Xin, const float* __restrict__ W,
                 const float* __restrict__ ba, const float* __restrict__ bb,
                 int N, int K) {
    float* C = (MODE == 0) ? g_pre1 : g_pre2;
    const float* X = (MODE == 0) ? Xin : (g_hist1 + H1);

    __shared__ float Xs[16][64];
    __shared__ float Ws[16][64];

    int tid = threadIdx.x;
    int tx = tid & 15;
    int ty = tid >> 4;
    int n0 = blockIdx.x * 64;
    int m0 = blockIdx.y * 64;

    float acc[4][4];
#pragma unroll
    for (int i = 0; i < 4; i++)
#pragma unroll
        for (int j = 0; j < 4; j++) acc[i][j] = 0.0f;

    for (int kk = 0; kk < K; kk += 16) {
#pragma unroll
        for (int i = tid; i < 1024; i += 256) {
            int r = i >> 4;
            int k = i & 15;
            Xs[k][r] = X[(size_t)(m0 + r) * K + kk + k];
            Ws[k][r] = W[(size_t)(n0 + r) * K + kk + k];
        }
        __syncthreads();
#pragma unroll
        for (int k = 0; k < 16; k++) {
            float4 a = *(const float4*)&Xs[k][ty * 4];
            float4 b = *(const float4*)&Ws[k][tx * 4];
            float av[4] = {a.x, a.y, a.z, a.w};
            float bv[4] = {b.x, b.y, b.z, b.w};
#pragma unroll
            for (int i = 0; i < 4; i++)
#pragma unroll
                for (int j = 0; j < 4; j++) acc[i][j] = fmaf(av[i], bv[j], acc[i][j]);
        }
        __syncthreads();
    }

#pragma unroll
    for (int i = 0; i < 4; i++) {
        int m = m0 + ty * 4 + i;
#pragma unroll
        for (int j = 0; j < 4; j++) {
            int n = n0 + tx * 4 + j;
            C[(size_t)m * N + n] = acc[i][j] + ba[n] + bb[n];
        }
    }
}

// ---------------- persistent LSTM recurrence (fp16 weights, fp32 math) ----------------
// 128 CTAs, single co-resident wave. One warp owns one hidden unit; cell state c
// lives in a lane-0 register across all 4096 steps. h history is write-once:
// step t reads slot t, writes slot t+1, arrives arr[t].
template <int HD, int PHASE>
__global__ void __launch_bounds__(HD / 4, 1)
lstm_kernel() {
    constexpr int WARPS = HD / 128;
    const float* pre  = (PHASE == 0) ? g_pre1  : g_pre2;
    float*       hist = (PHASE == 0) ? g_hist1 : g_hist2;
    unsigned*    arr  = (PHASE == 0) ? g_arr1  : g_arr2;
    const uint2* whh  = (PHASE == 0) ? g_whh1h : g_whh2h;

    __shared__ float4 hs[HD / 4];

    int tid  = threadIdx.x;
    int wid  = tid >> 5;
    int lane = tid & 31;
    int u = blockIdx.x * WARPS + wid;

    // each gate row is HD halfs = HD/4 uint2's
    const uint2* wi = whh + (size_t)(0 * HD + u) * (HD / 4);
    const uint2* wf = whh + (size_t)(1 * HD + u) * (HD / 4);
    const uint2* wg = whh + (size_t)(2 * HD + u) * (HD / 4);
    const uint2* wo = whh + (size_t)(3 * HD + u) * (HD / 4);

    float c = 0.0f;

    for (int t = 0; t < T_STEPS; t++) {
        // ---- acquire: wait for step t-1 completion across all CTAs ----
        if (t > 0 && tid == 0) {
            while (ld_acq_u32(&arr[t - 1]) < (unsigned)NCTA) {
                __nanosleep(64);   // back off: don't serialize the LTS atomic slot
            }
        }
        __syncthreads();

        // ---- stage h_prev (slot t) into SMEM, L1-bypassed ----
        const float4* hread = (const float4*)(hist + (size_t)t * HD);
        hs[tid] = ld_cg_f4(&hread[tid]);
        __syncthreads();

        // ---- 4 gate-row dot products (fp16 weights -> fp32 fma) ----
        float a0 = 0.f, a1 = 0.f, a2 = 0.f, a3 = 0.f;
#pragma unroll 4
        for (int i = 0; i < HD / 128; i++) {
            int c4 = (i << 5) + lane;
            float4 h4 = hs[c4];
            {
                uint2 p = wi[c4];
                float2 lo = __half22float2(*reinterpret_cast<__half2*>(&p.x));
                float2 hi = __half22float2(*reinterpret_cast<__half2*>(&p.y));
                a0 = fmaf(lo.x, h4.x, a0); a0 = fmaf(lo.y, h4.y, a0);
                a0 = fmaf(hi.x, h4.z, a0); a0 = fmaf(hi.y, h4.w, a0);
            }
            {
                uint2 p = wf[c4];
                float2 lo = __half22float2(*reinterpret_cast<__half2*>(&p.x));
                float2 hi = __half22float2(*reinterpret_cast<__half2*>(&p.y));
                a1 = fmaf(lo.x, h4.x, a1); a1 = fmaf(lo.y, h4.y, a1);
                a1 = fmaf(hi.x, h4.z, a1); a1 = fmaf(hi.y, h4.w, a1);
            }
            {
                uint2 p = wg[c4];
                float2 lo = __half22float2(*reinterpret_cast<__half2*>(&p.x));
                float2 hi = __half22float2(*reinterpret_cast<__half2*>(&p.y));
                a2 = fmaf(lo.x, h4.x, a2); a2 = fmaf(lo.y, h4.y, a2);
                a2 = fmaf(hi.x, h4.z, a2); a2 = fmaf(hi.y, h4.w, a2);
            }
            {
                uint2 p = wo[c4];
                float2 lo = __half22float2(*reinterpret_cast<__half2*>(&p.x));
                float2 hi = __half22float2(*reinterpret_cast<__half2*>(&p.y));
                a3 = fmaf(lo.x, h4.x, a3); a3 = fmaf(lo.y, h4.y, a3);
                a3 = fmaf(hi.x, h4.z, a3); a3 = fmaf(hi.y, h4.w, a3);
            }
        }
#pragma unroll
        for (int off = 16; off > 0; off >>= 1) {
            a0 += __shfl_xor_sync(0xFFFFFFFFu, a0, off);
            a1 += __shfl_xor_sync(0xFFFFFFFFu, a1, off);
            a2 += __shfl_xor_sync(0xFFFFFFFFu, a2, off);
            a3 += __shfl_xor_sync(0xFFFFFFFFu, a3, off);
        }

        // ---- state update + publish h into write-once slot t+1 ----
        if (lane == 0) {
            const float* prow = pre + (size_t)t * (4 * HD);
            float pi = prow[0 * HD + u] + a0;
            float pf = prow[1 * HD + u] + a1;
            float pg = prow[2 * HD + u] + a2;
            float po = prow[3 * HD + u] + a3;
            float iv = sigmoidf_(pi);
            float fv = sigmoidf_(pf);
            float gv = tanhf(pg);
            float ov = sigmoidf_(po);
            c = fv * c + iv * gv;
            float h = ov * tanhf(c);
            st_cg_f32(hist + (size_t)(t + 1) * HD + u, h);
        }

        // ---- release: each storer drains its OWN store, then tid0 signals ----
        __threadfence();
        __syncthreads();
        if (tid == 0) {
            atomicAdd(&arr[t], 1u);
        }
    }
}

// ---------------- head: two matvecs on final h2 (slot T of g_hist2) ----------------
__global__ void __launch_bounds__(256) head1_kernel(const float* __restrict__ w,
                                                    const float* __restrict__ b) {
    int wid = threadIdx.x >> 5, lane = threadIdx.x & 31;
    int o = blockIdx.x * 8 + wid;
    const float4* wr = (const float4*)(w + (size_t)o * H2);
    const float4* hv = (const float4*)(g_hist2 + (size_t)T_STEPS * H2);
    float a = 0.f;
#pragma unroll
    for (int i = 0; i < 16; i++) {
        float4 W4 = wr[(i << 5) + lane];
        float4 Hh = hv[(i << 5) + lane];
        a = fmaf(W4.x, Hh.x, a); a = fmaf(W4.y, Hh.y, a);
        a = fmaf(W4.z, Hh.z, a); a = fmaf(W4.w, Hh.w, a);
    }
#pragma unroll
    for (int off = 16; off > 0; off >>= 1) a += __shfl_xor_sync(0xFFFFFFFFu, a, off);
    if (lane == 0) g_mid[o] = a + b[o];
}

__global__ void __launch_bounds__(256) head2_kernel(const float* __restrict__ w,
                                                    const float* __restrict__ b,
                                                    float* __restrict__ out) {
    int wid = threadIdx.x >> 5, lane = threadIdx.x & 31;
    int o = blockIdx.x * 8 + wid;
    const float4* wr = (const float4*)(w + (size_t)o * (2 * OUT_SZ));
    const float4* mv = (const float4*)(g_mid);
    float a = 0.f;
#pragma unroll
    for (int i = 0; i < 8; i++) {
        float4 W4 = wr[(i << 5) + lane];
        float4 Mm = mv[(i << 5) + lane];
        a = fmaf(W4.x, Mm.x, a); a = fmaf(W4.y, Mm.y, a);
        a = fmaf(W4.z, Mm.z, a); a = fmaf(W4.w, Mm.w, a);
    }
#pragma unroll
    for (int off = 16; off > 0; off >>= 1) a += __shfl_xor_sync(0xFFFFFFFFu, a, off);
    if (lane == 0) out[o] = a + b[o];
}

// ---------------- launch ----------------
extern "C" void kernel_launch(void* const* d_in, const int* in_sizes, int n_in,
                              void* d_out, int out_size) {
    const float* input_seq = (const float*)d_in[0];
    const float* w_ih1     = (const float*)d_in[1];
    const float* w_hh1     = (const float*)d_in[2];
    const float* b_ih1     = (const float*)d_in[3];
    const float* b_hh1     = (const float*)d_in[4];
    const float* w_ih2     = (const float*)d_in[5];
    const float* w_hh2     = (const float*)d_in[6];
    const float* b_ih2     = (const float*)d_in[7];
    const float* b_hh2     = (const float*)d_in[8];
    const float* w_l1      = (const float*)d_in[9];
    const float* b_l1      = (const float*)d_in[10];
    const float* w_l2      = (const float*)d_in[11];
    const float* b_l2      = (const float*)d_in[12];
    float* out = (float*)d_out;

    // 1) reset barriers + zero h0 slots; convert recurrent weights to fp16
    init_kernel<<<16, 256>>>();
    convert_w_kernel<<<4096, 256>>>(w_hh1, w_hh2);

    // 2) lstm1 input projection: g_pre1[T, 4*H1]
    {
        dim3 grid(4 * H1 / 64, T_STEPS / 64);
        gemm_bias_kernel<0><<<grid, 256>>>(input_seq, w_ih1, b_ih1, b_hh1,
                                           4 * H1, IN_SZ);
    }

    // 3) lstm1 recurrence (persistent, 128 CTAs x 256 threads)
    lstm_kernel<H1, 0><<<NCTA, H1 / 4>>>();

    // 4) lstm2 input projection: g_pre2[T, 4*H2] from h1 history
    {
        dim3 grid(4 * H2 / 64, T_STEPS / 64);
        gemm_bias_kernel<1><<<grid, 256>>>(nullptr, w_ih2, b_ih2, b_hh2,
                                           4 * H2, H1);
    }

    // 5) lstm2 recurrence (persistent, 128 CTAs x 512 threads)
    lstm_kernel<H2, 1><<<NCTA, H2 / 4>>>();

    // 6) head on final h2
    head1_kernel<<<128, 256>>>(w_l1, b_l1);
    head2_kernel<<<64, 256>>>(w_l2, b_l2, out);
}